// round 13
// baseline (speedup 1.0000x reference)
#include <cuda_runtime.h>
#include <cuda_fp16.h>
#include <cstdint>

// B=16,H=128 -> 2048 groups; per group X[128,256], D=32.
#define NTHR 256

// ---------------- SMEM layout (bytes) ----------------
#define XT_OFF  0                    // X^T frag image [32 ch-tiles][8 kt][32 lanes] u2 = 65,536
#define WB0     65536                // weight buffer 0 (17,408)
#define WCHUNK  17408
#define WB1     82944                // weight buffer 1
#define K_OFF   100352               // K image [128][96] = 12,288
#define KSTR    96
#define XSTR    544                  // weight-image row stride
#define SMEM_BYTES 112640            // -> 2 CTAs/SM

// k-permutation: (2q,2q+1,2q+8,2q+9) contiguous per 16-block
__device__ __forceinline__ int kslot(int k) {
    return (k & ~15) | (((k >> 1) & 3) << 2) | (((k >> 3) & 1) << 1) | (k & 1);
}

// 10 weight-chunk images: 0=Wq, 1=Wk, 2..9=Wv col-chunks of 32 (rows n, kslot k)
__device__ __align__(16) unsigned char g_wimg[10 * WCHUNK];

__device__ __forceinline__ uint32_t smem_u32(const void* p) {
    uint32_t a;
    asm("{ .reg .u64 t; cvta.to.shared.u64 t, %1; cvt.u32.u64 %0, t; }" : "=r"(a) : "l"(p));
    return a;
}
__device__ __forceinline__ void cp16(void* sdst, const void* gsrc) {
    asm volatile("cp.async.cg.shared.global [%0], [%1], 16;"
                 :: "r"(smem_u32(sdst)), "l"(gsrc));
}
#define CP_COMMIT() asm volatile("cp.async.commit_group;" ::: "memory")
#define CP_WAIT0()  asm volatile("cp.async.wait_group 0;" ::: "memory")

__device__ __forceinline__ void mma16816(float* c, uint32_t a0, uint32_t a1,
                                         uint32_t a2, uint32_t a3,
                                         uint32_t b0, uint32_t b1) {
    asm volatile(
        "mma.sync.aligned.m16n8k16.row.col.f32.f16.f16.f32 "
        "{%0,%1,%2,%3},{%4,%5,%6,%7},{%8,%9},{%0,%1,%2,%3};"
        : "+f"(c[0]), "+f"(c[1]), "+f"(c[2]), "+f"(c[3])
        : "r"(a0), "r"(a1), "r"(a2), "r"(a3), "r"(b0), "r"(b1));
}
__device__ __forceinline__ uint32_t packh(float x, float y) {
    __half2 p = __floats2half2_rn(x, y);
    return *reinterpret_cast<uint32_t*>(&p);
}

// =============== prep: weights -> fp16 SMEM-image chunks (R9 layout) ===============
__global__ void prep_weights(const float* __restrict__ Wq, const float* __restrict__ Wk,
                             const float* __restrict__ Wv) {
    int idx = blockIdx.x * 256 + threadIdx.x;   // 81920
    int chunk = idx >> 13;
    int n = (idx >> 8) & 31;
    int k = idx & 255;
    float w;
    if (chunk == 0)      w = Wq[k * 32 + n];
    else if (chunk == 1) w = Wk[k * 32 + n];
    else                 w = Wv[k * 256 + (chunk - 2) * 32 + n];
    unsigned off = (unsigned)chunk * WCHUNK + (unsigned)n * XSTR + (unsigned)kslot(k) * 2;
    *(__half*)(g_wimg + off) = __float2half(w);
}

// =============== main: one CTA (8 warps) per (b,h) group, 2 CTAs/SM ===============
__global__ __launch_bounds__(NTHR, 2)
void attn_mma_kernel(const float* __restrict__ X,
                     const float* __restrict__ bq, const float* __restrict__ bk,
                     const float* __restrict__ bv, float* __restrict__ out) {
    extern __shared__ unsigned char sm[];
    const int t = threadIdx.x, w = t >> 5, lane = t & 31;
    const int q = lane & 3, lq = lane >> 2;
    const int R = w * 16;
    const long long g = blockIdx.x;
    const float* Xg = X + g * 32768LL;
    float* Og = out + g * 32768LL;

    // issue Wq -> WB0, Wk -> WB1
    for (int i = t; i < WCHUNK / 16; i += NTHR) {
        cp16(sm + WB0 + i * 16, g_wimg + i * 16);
        cp16(sm + WB1 + i * 16, g_wimg + WCHUNK + i * 16);
    }
    CP_COMMIT();

    // ---- XT build: X^T fp16 frag image (64 tiles/warp) ----
    // tile: 8 channels x 4 token-pairs; lane -> (c = cbase+(lane>>2), jp = jbase+(lane&3))
    {
        const int lr = lane >> 2, lc = lane & 3;
        #pragma unroll 4
        for (int it = 0; it < 64; it++) {
            int ti = w * 64 + it;
            int cbase = (ti & 31) * 8;
            int jbase = (ti >> 5) * 4;
            int c = cbase + lr;
            int jp = jbase + lc;
            float x0 = Xg[(2 * jp) * 256 + c];
            float x1 = Xg[(2 * jp + 1) * 256 + c];
            int kt = jp >> 3;
            int wsel = (jp >> 2) & 1;
            unsigned addr = XT_OFF +
                (unsigned)((((c >> 3) * 8 + kt) * 32 + (c & 7) * 4 + lc) * 8 + wsel * 4);
            *(uint32_t*)(sm + addr) = packh(x0, x1);
        }
    }
    CP_WAIT0();
    __syncthreads();   // [S0] XT built; Wq/Wk landed & visible

    // ---------------- fused Q + K projection (A-frags direct from gmem) ----------
    float Cq[4][4], Ck[4][4];
    #pragma unroll
    for (int n = 0; n < 4; n++) {
        Cq[n][0] = Cq[n][1] = Cq[n][2] = Cq[n][3] = 0.f;
        Ck[n][0] = Ck[n][1] = Ck[n][2] = Ck[n][3] = 0.f;
    }
    {
        const float2* xr0 = (const float2*)(Xg + (R + lq) * 256);
        const float2* xr1 = xr0 + 1024;   // +8 rows
        #pragma unroll 4
        for (int kt = 0; kt < 16; kt++) {
            float2 p0 = xr0[kt * 8 + q];
            float2 p1 = xr1[kt * 8 + q];
            float2 p2 = xr0[kt * 8 + q + 4];
            float2 p3 = xr1[kt * 8 + q + 4];
            uint32_t a0 = packh(p0.x, p0.y), a1 = packh(p1.x, p1.y);
            uint32_t a2 = packh(p2.x, p2.y), a3 = packh(p3.x, p3.y);
            unsigned ko = kt * 32 + q * 8;
            #pragma unroll
            for (int nt = 0; nt < 4; nt++) {
                uint2 bqf = *(const uint2*)(sm + WB0 + (unsigned)(nt * 8 + lq) * XSTR + ko);
                uint2 bkf = *(const uint2*)(sm + WB1 + (unsigned)(nt * 8 + lq) * XSTR + ko);
                mma16816(Cq[nt], a0, a1, a2, a3, bqf.x, bqf.y);
                mma16816(Ck[nt], a0, a1, a2, a3, bkf.x, bkf.y);
            }
        }
    }
    // +bq, repack into scores A-fragments
    uint32_t qh[2][4];
    #pragma unroll
    for (int nt = 0; nt < 4; nt++) {
        float2 bb = *(const float2*)(bq + nt * 8 + 2 * q);
        Cq[nt][0] += bb.x; Cq[nt][1] += bb.y; Cq[nt][2] += bb.x; Cq[nt][3] += bb.y;
    }
    #pragma unroll
    for (int kt = 0; kt < 2; kt++) {
        qh[kt][0] = packh(Cq[2*kt][0],   Cq[2*kt][1]);
        qh[kt][1] = packh(Cq[2*kt][2],   Cq[2*kt][3]);
        qh[kt][2] = packh(Cq[2*kt+1][0], Cq[2*kt+1][1]);
        qh[kt][3] = packh(Cq[2*kt+1][2], Cq[2*kt+1][3]);
    }
    // write K image (+bk)
    #pragma unroll
    for (int nt = 0; nt < 4; nt++) {
        float2 bb = *(const float2*)(bk + nt * 8 + 2 * q);
        float c0 = Ck[nt][0] + bb.x, c1 = Ck[nt][1] + bb.y;
        float c2 = Ck[nt][2] + bb.x, c3 = Ck[nt][3] + bb.y;
        int p = kslot(nt * 8 + 2 * q) * 2;
        *(uint32_t*)(sm + K_OFF + (unsigned)(R + lq) * KSTR + p)     = packh(c0, c1);
        *(uint32_t*)(sm + K_OFF + (unsigned)(R + lq + 8) * KSTR + p) = packh(c2, c3);
    }
    __syncthreads();   // [S1] proj done reading WB; K visible

    // issue Wv chunk 0 -> WB0 (lands during scores/softmax/Y)
    for (int i = t; i < WCHUNK / 16; i += NTHR)
        cp16(sm + WB0 + i * 16, g_wimg + 2 * WCHUNK + i * 16);
    CP_COMMIT();

    // ---------------- scores S = Q @ K^T ----------------
    float Cs[16][4];
    #pragma unroll
    for (int n = 0; n < 16; n++) { Cs[n][0] = Cs[n][1] = Cs[n][2] = Cs[n][3] = 0.f; }
    #pragma unroll
    for (int ng = 0; ng < 4; ng++) {
        #pragma unroll
        for (int kt = 0; kt < 2; kt++) {
            unsigned ko = kt * 32 + q * 8;
            #pragma unroll
            for (int ni = 0; ni < 4; ni++) {
                int nt = ng * 4 + ni;
                uint2 bh = *(const uint2*)(sm + K_OFF + (unsigned)(nt * 8 + lq) * KSTR + ko);
                mma16816(Cs[nt], qh[kt][0], qh[kt][1], qh[kt][2], qh[kt][3], bh.x, bh.y);
            }
        }
    }

    // ---------------- softmax (registers + quad shuffles) ----------------
    {
        float m0 = -1e30f, m1 = -1e30f;
        #pragma unroll
        for (int nt = 0; nt < 16; nt++) {
            m0 = fmaxf(m0, fmaxf(Cs[nt][0], Cs[nt][1]));
            m1 = fmaxf(m1, fmaxf(Cs[nt][2], Cs[nt][3]));
        }
        m0 = fmaxf(m0, __shfl_xor_sync(0xffffffffu, m0, 1));
        m0 = fmaxf(m0, __shfl_xor_sync(0xffffffffu, m0, 2));
        m1 = fmaxf(m1, __shfl_xor_sync(0xffffffffu, m1, 1));
        m1 = fmaxf(m1, __shfl_xor_sync(0xffffffffu, m1, 2));
        float s0 = 0.f, s1 = 0.f;
        #pragma unroll
        for (int nt = 0; nt < 16; nt++) {
            Cs[nt][0] = __expf(Cs[nt][0] - m0); Cs[nt][1] = __expf(Cs[nt][1] - m0);
            Cs[nt][2] = __expf(Cs[nt][2] - m1); Cs[nt][3] = __expf(Cs[nt][3] - m1);
            s0 += Cs[nt][0] + Cs[nt][1];
            s1 += Cs[nt][2] + Cs[nt][3];
        }
        s0 += __shfl_xor_sync(0xffffffffu, s0, 1);
        s0 += __shfl_xor_sync(0xffffffffu, s0, 2);
        s1 += __shfl_xor_sync(0xffffffffu, s1, 1);
        s1 += __shfl_xor_sync(0xffffffffu, s1, 2);
        const float i0 = 1.f / s0, i1 = 1.f / s1;
        #pragma unroll
        for (int nt = 0; nt < 16; nt++) {
            Cs[nt][0] *= i0; Cs[nt][1] *= i0; Cs[nt][2] *= i1; Cs[nt][3] *= i1;
        }
    }
    // attn A-frags
    uint32_t ah[8][4];
    #pragma unroll
    for (int kt = 0; kt < 8; kt++) {
        ah[kt][0] = packh(Cs[2*kt][0],   Cs[2*kt][1]);
        ah[kt][1] = packh(Cs[2*kt][2],   Cs[2*kt][3]);
        ah[kt][2] = packh(Cs[2*kt+1][0], Cs[2*kt+1][1]);
        ah[kt][3] = packh(Cs[2*kt+1][2], Cs[2*kt+1][3]);
    }

    // ---------------- Y = attn @ X^T (result -> fp16 A-frag registers) ----------
    uint32_t yh[16][4];
    #pragma unroll
    for (int nb = 0; nb < 4; nb++) {
        float Cy[8][4];
        #pragma unroll
        for (int n = 0; n < 8; n++) { Cy[n][0] = Cy[n][1] = Cy[n][2] = Cy[n][3] = 0.f; }
        #pragma unroll
        for (int kt = 0; kt < 8; kt++) {
            #pragma unroll
            for (int np = 0; np < 8; np++) {
                int ntc = nb * 8 + np;
                uint2 bf = *(const uint2*)(sm + XT_OFF + (unsigned)(((ntc * 8 + kt) * 32 + lane) * 8));
                mma16816(Cy[np], ah[kt][0], ah[kt][1], ah[kt][2], ah[kt][3], bf.x, bf.y);
            }
        }
        #pragma unroll
        for (int i = 0; i < 4; i++) {
            int kt2 = nb * 4 + i;
            yh[kt2][0] = packh(Cy[2*i][0],   Cy[2*i][1]);
            yh[kt2][1] = packh(Cy[2*i][2],   Cy[2*i][3]);
            yh[kt2][2] = packh(Cy[2*i+1][0], Cy[2*i+1][1]);
            yh[kt2][3] = packh(Cy[2*i+1][2], Cy[2*i+1][3]);
        }
    }

    // ---------------- O chunks = Y @ Wv chunk (1 sync per chunk) ----------------
    #pragma unroll 1
    for (int c = 0; c < 8; c++) {
        CP_WAIT0();
        __syncthreads();   // Wv(c) visible to all; chunk c-1 reads done everywhere
        if (c < 7) {
            unsigned dst = ((c + 1) & 1) ? WB1 : WB0;
            const unsigned char* src = g_wimg + (unsigned)(c + 3) * WCHUNK;
            for (int i = t; i < WCHUNK / 16; i += NTHR) cp16(sm + dst + i * 16, src + i * 16);
            CP_COMMIT();
        }
        const unsigned buf = (c & 1) ? WB1 : WB0;
        float Co[4][4];
        #pragma unroll
        for (int n = 0; n < 4; n++) { Co[n][0] = Co[n][1] = Co[n][2] = Co[n][3] = 0.f; }
        #pragma unroll 4
        for (int kt2 = 0; kt2 < 16; kt2++) {
            unsigned ko = kt2 * 32 + q * 8;
            #pragma unroll
            for (int nt = 0; nt < 4; nt++) {
                uint2 bf = *(const uint2*)(sm + buf + (unsigned)(nt * 8 + lq) * XSTR + ko);
                mma16816(Co[nt], yh[kt2][0], yh[kt2][1], yh[kt2][2], yh[kt2][3], bf.x, bf.y);
            }
        }
        #pragma unroll
        for (int nt = 0; nt < 4; nt++) {
            int col = c * 32 + nt * 8 + 2 * q;
            float2 bb = *(const float2*)(bv + col);
            *(float2*)(Og + (long long)(R + lq) * 256 + col) =
                make_float2(Co[nt][0] + bb.x, Co[nt][1] + bb.y);
            *(float2*)(Og + (long long)(R + 8 + lq) * 256 + col) =
                make_float2(Co[nt][2] + bb.x, Co[nt][3] + bb.y);
        }
    }
}

extern "C" void kernel_launch(void* const* d_in, const int* in_sizes, int n_in,
                              void* d_out, int out_size) {
    const float* X  = (const float*)d_in[0];
    const float* Wq = (const float*)d_in[1];
    const float* bq = (const float*)d_in[2];
    const float* Wk = (const float*)d_in[3];
    const float* bk = (const float*)d_in[4];
    const float* Wv = (const float*)d_in[5];
    const float* bv = (const float*)d_in[6];
    float* out = (float*)d_out;

    const int groups = in_sizes[0] / (128 * 256);   // 2048

    prep_weights<<<320, 256>>>(Wq, Wk, Wv);

    cudaFuncSetAttribute(attn_mma_kernel,
                         cudaFuncAttributeMaxDynamicSharedMemorySize, SMEM_BYTES);
    attn_mma_kernel<<<groups, NTHR, SMEM_BYTES>>>(X, bq, bk, bv, out);
}

// round 14
// speedup vs baseline: 1.0660x; 1.0660x over previous
#include <cuda_runtime.h>
#include <cuda_fp16.h>
#include <cstdint>

// B=16,H=128 -> 2048 groups; per group X[128,256], D=32.
#define NTHR 256

// ---------------- SMEM layout (bytes) ----------------
#define WB0     0                    // weight buffer 0 (17,408)
#define WCHUNK  17408
#define WB1     17408                // weight buffer 1
#define K_OFF   34816                // K image [128][96] = 12,288
#define KSTR    96
#define VT_BASE 47104                // 8 frag-major VT images, 8,192 each = 65,536
#define SMEM_BYTES 112640            // -> 2 CTAs/SM (limit 116,224)
#define XSTR    544                  // weight-image row stride

// k-permutation: (2q,2q+1,2q+8,2q+9) contiguous per 16-block
__device__ __forceinline__ int kslot(int k) {
    return (k & ~15) | (((k >> 1) & 3) << 2) | (((k >> 3) & 1) << 1) | (k & 1);
}

// 10 weight-chunk images: 0=Wq, 1=Wk, 2..9=Wv col-chunks of 32 (rows n, kslot k)
__device__ __align__(16) unsigned char g_wimg[10 * WCHUNK];

__device__ __forceinline__ uint32_t smem_u32(const void* p) {
    uint32_t a;
    asm("{ .reg .u64 t; cvta.to.shared.u64 t, %1; cvt.u32.u64 %0, t; }" : "=r"(a) : "l"(p));
    return a;
}
__device__ __forceinline__ void cp16(void* sdst, const void* gsrc) {
    asm volatile("cp.async.cg.shared.global [%0], [%1], 16;"
                 :: "r"(smem_u32(sdst)), "l"(gsrc));
}
#define CP_COMMIT() asm volatile("cp.async.commit_group;" ::: "memory")
#define CP_WAIT0()  asm volatile("cp.async.wait_group 0;" ::: "memory")

__device__ __forceinline__ void mma16816(float* c, uint32_t a0, uint32_t a1,
                                         uint32_t a2, uint32_t a3,
                                         uint32_t b0, uint32_t b1) {
    asm volatile(
        "mma.sync.aligned.m16n8k16.row.col.f32.f16.f16.f32 "
        "{%0,%1,%2,%3},{%4,%5,%6,%7},{%8,%9},{%0,%1,%2,%3};"
        : "+f"(c[0]), "+f"(c[1]), "+f"(c[2]), "+f"(c[3])
        : "r"(a0), "r"(a1), "r"(a2), "r"(a3), "r"(b0), "r"(b1));
}
__device__ __forceinline__ uint32_t packh(float x, float y) {
    __half2 p = __floats2half2_rn(x, y);
    return *reinterpret_cast<uint32_t*>(&p);
}

// =============== prep: weights -> fp16 SMEM-image chunks (R9 layout) ===============
__global__ void prep_weights(const float* __restrict__ Wq, const float* __restrict__ Wk,
                             const float* __restrict__ Wv) {
    int idx = blockIdx.x * 256 + threadIdx.x;   // 81920
    int chunk = idx >> 13;
    int n = (idx >> 8) & 31;
    int k = idx & 255;
    float w;
    if (chunk == 0)      w = Wq[k * 32 + n];
    else if (chunk == 1) w = Wk[k * 32 + n];
    else                 w = Wv[k * 256 + (chunk - 2) * 32 + n];
    unsigned off = (unsigned)chunk * WCHUNK + (unsigned)n * XSTR + (unsigned)kslot(k) * 2;
    *(__half*)(g_wimg + off) = __float2half(w);
}

// =============== main: one CTA (8 warps) per (b,h) group, 2 CTAs/SM ===============
__global__ __launch_bounds__(NTHR, 2)
void attn_mma_kernel(const float* __restrict__ X,
                     const float* __restrict__ bq, const float* __restrict__ bk,
                     const float* __restrict__ bv, float* __restrict__ out) {
    extern __shared__ unsigned char sm[];
    const int t = threadIdx.x, w = t >> 5, lane = t & 31;
    const int q = lane & 3, lq = lane >> 2;
    const int R = w * 16;
    const long long g = blockIdx.x;
    const float* Xg = X + g * 32768LL;
    float* Og = out + g * 32768LL;

    // issue Wq -> WB0, Wk -> WB1
    for (int i = t; i < WCHUNK / 16; i += NTHR) {
        cp16(sm + WB0 + i * 16, g_wimg + i * 16);
        cp16(sm + WB1 + i * 16, g_wimg + WCHUNK + i * 16);
    }
    CP_COMMIT();

    // ---- load X A-fragments ONCE from gmem into registers (64 regs) ----
    // Xa[kt] = (a0: row R+lq k-lo | a1: row R+lq+8 k-lo | a2: row R+lq k-hi | a3: row R+lq+8 k-hi)
    uint4 Xa[16];
    {
        const float2* xr0 = (const float2*)(Xg + (R + lq) * 256);
        const float2* xr1 = xr0 + 1024;   // +8 rows
        #pragma unroll
        for (int kt = 0; kt < 16; kt++) {
            float2 p0 = xr0[kt * 8 + q];
            float2 p1 = xr1[kt * 8 + q];
            float2 p2 = xr0[kt * 8 + q + 4];
            float2 p3 = xr1[kt * 8 + q + 4];
            Xa[kt] = make_uint4(packh(p0.x, p0.y), packh(p1.x, p1.y),
                                packh(p2.x, p2.y), packh(p3.x, p3.y));
        }
    }
    CP_WAIT0();
    __syncthreads();   // [S0] Wq/Wk visible

    // ---------------- fused Q + K projection (A from regs) ----------------
    float Cq[4][4], Ck[4][4];
    #pragma unroll
    for (int n = 0; n < 4; n++) {
        Cq[n][0] = Cq[n][1] = Cq[n][2] = Cq[n][3] = 0.f;
        Ck[n][0] = Ck[n][1] = Ck[n][2] = Ck[n][3] = 0.f;
    }
    #pragma unroll 4
    for (int kt = 0; kt < 16; kt++) {
        unsigned ko = kt * 32 + q * 8;
        #pragma unroll
        for (int nt = 0; nt < 4; nt++) {
            uint2 bqf = *(const uint2*)(sm + WB0 + (unsigned)(nt * 8 + lq) * XSTR + ko);
            uint2 bkf = *(const uint2*)(sm + WB1 + (unsigned)(nt * 8 + lq) * XSTR + ko);
            mma16816(Cq[nt], Xa[kt].x, Xa[kt].y, Xa[kt].z, Xa[kt].w, bqf.x, bqf.y);
            mma16816(Ck[nt], Xa[kt].x, Xa[kt].y, Xa[kt].z, Xa[kt].w, bkf.x, bkf.y);
        }
    }
    // +bq, repack into scores A-fragments
    uint32_t qh[2][4];
    #pragma unroll
    for (int nt = 0; nt < 4; nt++) {
        float2 bb = *(const float2*)(bq + nt * 8 + 2 * q);
        Cq[nt][0] += bb.x; Cq[nt][1] += bb.y; Cq[nt][2] += bb.x; Cq[nt][3] += bb.y;
    }
    #pragma unroll
    for (int kt = 0; kt < 2; kt++) {
        qh[kt][0] = packh(Cq[2*kt][0],   Cq[2*kt][1]);
        qh[kt][1] = packh(Cq[2*kt][2],   Cq[2*kt][3]);
        qh[kt][2] = packh(Cq[2*kt+1][0], Cq[2*kt+1][1]);
        qh[kt][3] = packh(Cq[2*kt+1][2], Cq[2*kt+1][3]);
    }
    // write K image (+bk)
    #pragma unroll
    for (int nt = 0; nt < 4; nt++) {
        float2 bb = *(const float2*)(bk + nt * 8 + 2 * q);
        float c0 = Ck[nt][0] + bb.x, c1 = Ck[nt][1] + bb.y;
        float c2 = Ck[nt][2] + bb.x, c3 = Ck[nt][3] + bb.y;
        int p = kslot(nt * 8 + 2 * q) * 2;
        *(uint32_t*)(sm + K_OFF + (unsigned)(R + lq) * KSTR + p)     = packh(c0, c1);
        *(uint32_t*)(sm + K_OFF + (unsigned)(R + lq + 8) * KSTR + p) = packh(c2, c3);
    }
    __syncthreads();   // [S1] proj reads of WB0/WB1 done; K visible

    // issue Wv0 -> WB0
    for (int i = t; i < WCHUNK / 16; i += NTHR)
        cp16(sm + WB0 + i * 16, g_wimg + 2 * WCHUNK + i * 16);
    CP_COMMIT();

    // V-transpose constants (R12-verified frag-major mapping)
    const bool oddlq = (lq & 1);
    const unsigned vslotbase = (unsigned)((2 * q + (oddlq ? 1 : 0)) * 4 + (lq >> 1)) * 8;

    // ---------------- Vproj phase: 8 chunks, A from regs, 1 sync/chunk ----------
    #pragma unroll 1
    for (int c = 0; c < 8; c++) {
        CP_WAIT0();
        __syncthreads();   // Wv(c) visible; all warps done Vproj(c-1) buffer reads
        if (c < 7) {
            unsigned dst = ((c + 1) & 1) ? WB1 : WB0;
            const unsigned char* src = g_wimg + (unsigned)(c + 3) * WCHUNK;
            for (int i = t; i < WCHUNK / 16; i += NTHR) cp16(sm + dst + i * 16, src + i * 16);
            CP_COMMIT();
        }
        const unsigned buf = (c & 1) ? WB1 : WB0;
        float Cv[4][4];
        #pragma unroll
        for (int n = 0; n < 4; n++) { Cv[n][0] = Cv[n][1] = Cv[n][2] = Cv[n][3] = 0.f; }
        #pragma unroll 4
        for (int kt = 0; kt < 16; kt++) {
            unsigned ko = kt * 32 + q * 8;
            #pragma unroll
            for (int nt = 0; nt < 4; nt++) {
                uint2 bf = *(const uint2*)(sm + buf + (unsigned)(nt * 8 + lq) * XSTR + ko);
                mma16816(Cv[nt], Xa[kt].x, Xa[kt].y, Xa[kt].z, Xa[kt].w, bf.x, bf.y);
            }
        }
        // VT(c) store: shfl pair-exchange -> frag-major image (warp w = frag kt=w)
        const unsigned vtw = VT_BASE + (unsigned)c * 8192;
        #pragma unroll
        for (int nt = 0; nt < 4; nt++) {
            float v0 = Cv[nt][0], v1 = Cv[nt][1], v2 = Cv[nt][2], v3 = Cv[nt][3];
            float sendA = oddlq ? v0 : v1;
            float recvA = __shfl_xor_sync(0xffffffffu, sendA, 4);
            float sendB = oddlq ? v2 : v3;
            float recvB = __shfl_xor_sync(0xffffffffu, sendB, 4);
            float a0 = oddlq ? recvA : v0, a1 = oddlq ? v1 : recvA;
            float b0 = oddlq ? recvB : v2, b1 = oddlq ? v3 : recvB;
            unsigned fb = vtw + (unsigned)(w * 4 + nt) * 256 + vslotbase;
            *(uint32_t*)(sm + fb)     = packh(a0, a1);
            *(uint32_t*)(sm + fb + 4) = packh(b0, b1);
        }
    }
    __syncthreads();   // [S10] all VT images visible

    // ---------------- scores S = Q @ K^T ----------------
    float Cs[16][4];
    #pragma unroll
    for (int n = 0; n < 16; n++) { Cs[n][0] = Cs[n][1] = Cs[n][2] = Cs[n][3] = 0.f; }
    #pragma unroll
    for (int ng = 0; ng < 4; ng++) {
        #pragma unroll
        for (int kt = 0; kt < 2; kt++) {
            unsigned ko = kt * 32 + q * 8;
            #pragma unroll
            for (int ni = 0; ni < 4; ni++) {
                int nt = ng * 4 + ni;
                uint2 bh = *(const uint2*)(sm + K_OFF + (unsigned)(nt * 8 + lq) * KSTR + ko);
                mma16816(Cs[nt], qh[kt][0], qh[kt][1], qh[kt][2], qh[kt][3], bh.x, bh.y);
            }
        }
    }

    // ---------------- softmax (registers + quad shuffles) ----------------
    {
        float m0 = -1e30f, m1 = -1e30f;
        #pragma unroll
        for (int nt = 0; nt < 16; nt++) {
            m0 = fmaxf(m0, fmaxf(Cs[nt][0], Cs[nt][1]));
            m1 = fmaxf(m1, fmaxf(Cs[nt][2], Cs[nt][3]));
        }
        m0 = fmaxf(m0, __shfl_xor_sync(0xffffffffu, m0, 1));
        m0 = fmaxf(m0, __shfl_xor_sync(0xffffffffu, m0, 2));
        m1 = fmaxf(m1, __shfl_xor_sync(0xffffffffu, m1, 1));
        m1 = fmaxf(m1, __shfl_xor_sync(0xffffffffu, m1, 2));
        float s0 = 0.f, s1 = 0.f;
        #pragma unroll
        for (int nt = 0; nt < 16; nt++) {
            Cs[nt][0] = __expf(Cs[nt][0] - m0); Cs[nt][1] = __expf(Cs[nt][1] - m0);
            Cs[nt][2] = __expf(Cs[nt][2] - m1); Cs[nt][3] = __expf(Cs[nt][3] - m1);
            s0 += Cs[nt][0] + Cs[nt][1];
            s1 += Cs[nt][2] + Cs[nt][3];
        }
        s0 += __shfl_xor_sync(0xffffffffu, s0, 1);
        s0 += __shfl_xor_sync(0xffffffffu, s0, 2);
        s1 += __shfl_xor_sync(0xffffffffu, s1, 1);
        s1 += __shfl_xor_sync(0xffffffffu, s1, 2);
        const float i0 = 1.f / s0, i1 = 1.f / s1;
        #pragma unroll
        for (int nt = 0; nt < 16; nt++) {
            Cs[nt][0] *= i0; Cs[nt][1] *= i0; Cs[nt][2] *= i1; Cs[nt][3] *= i1;
        }
    }
    // attn A-frags
    uint32_t ah[8][4];
    #pragma unroll
    for (int kt = 0; kt < 8; kt++) {
        ah[kt][0] = packh(Cs[2*kt][0],   Cs[2*kt][1]);
        ah[kt][1] = packh(Cs[2*kt][2],   Cs[2*kt][3]);
        ah[kt][2] = packh(Cs[2*kt+1][0], Cs[2*kt+1][1]);
        ah[kt][3] = packh(Cs[2*kt+1][2], Cs[2*kt+1][3]);
    }

    // ---------------- AV phase: 8 chunks, ZERO barriers ----------------
    const unsigned lko8 = (unsigned)lane * 8;
    #pragma unroll 1
    for (int c = 0; c < 8; c++) {
        const unsigned vt = VT_BASE + (unsigned)c * 8192;
        float Co[4][4];
        #pragma unroll
        for (int n = 0; n < 4; n++) { Co[n][0] = Co[n][1] = Co[n][2] = Co[n][3] = 0.f; }
        #pragma unroll
        for (int kt = 0; kt < 8; kt++) {
            #pragma unroll
            for (int nt = 0; nt < 4; nt++) {
                uint2 bh = *(const uint2*)(sm + vt + (unsigned)(kt * 4 + nt) * 256 + lko8);
                mma16816(Co[nt], ah[kt][0], ah[kt][1], ah[kt][2], ah[kt][3], bh.x, bh.y);
            }
        }
        #pragma unroll
        for (int nt = 0; nt < 4; nt++) {
            int col = c * 32 + nt * 8 + 2 * q;
            float2 bb = *(const float2*)(bv + col);
            *(float2*)(Og + (long long)(R + lq) * 256 + col) =
                make_float2(Co[nt][0] + bb.x, Co[nt][1] + bb.y);
            *(float2*)(Og + (long long)(R + 8 + lq) * 256 + col) =
                make_float2(Co[nt][2] + bb.x, Co[nt][3] + bb.y);
        }
    }
}

extern "C" void kernel_launch(void* const* d_in, const int* in_sizes, int n_in,
                              void* d_out, int out_size) {
    const float* X  = (const float*)d_in[0];
    const float* Wq = (const float*)d_in[1];
    const float* bq = (const float*)d_in[2];
    const float* Wk = (const float*)d_in[3];
    const float* bk = (const float*)d_in[4];
    const float* Wv = (const float*)d_in[5];
    const float* bv = (const float*)d_in[6];
    float* out = (float*)d_out;

    const int groups = in_sizes[0] / (128 * 256);   // 2048

    prep_weights<<<320, 256>>>(Wq, Wk, Wv);

    cudaFuncSetAttribute(attn_mma_kernel,
                         cudaFuncAttributeMaxDynamicSharedMemorySize, SMEM_BYTES);
    attn_mma_kernel<<<groups, NTHR, SMEM_BYTES>>>(X, bq, bk, bv, out);
}

// round 15
// speedup vs baseline: 1.1653x; 1.0932x over previous
#include <cuda_runtime.h>
#include <cuda_fp16.h>
#include <cstdint>

// B=16,H=128 -> 2048 groups; per group X[128,256], D=32.
#define NTHR 256

// ---------------- SMEM layout (bytes) ----------------
// region0 [0..65,536): X frag image (phase A) then 8 VT frag images (phase B)
#define XF_OFF  0
#define VT_BASE 0
#define WB0     65536                // weight buffer 0 (17,408)
#define WCHUNK  17408
#define WB1     82944                // weight buffer 1
#define K_OFF   100352               // K image [128][96] = 12,288
#define KSTR    96
#define XSTR    544                  // weight-image row stride
#define SMEM_BYTES 112640            // -> 2 CTAs/SM (limit 116,224)

// k-permutation for weight/K images: (2q,2q+1,2q+8,2q+9) contiguous per 16-block
__device__ __forceinline__ int kslot(int k) {
    return (k & ~15) | (((k >> 1) & 3) << 2) | (((k >> 3) & 1) << 1) | (k & 1);
}

// 10 weight-chunk images: 0=Wq, 1=Wk, 2..9=Wv col-chunks of 32 (rows n, kslot k)
__device__ __align__(16) unsigned char g_wimg[10 * WCHUNK];

__device__ __forceinline__ uint32_t smem_u32(const void* p) {
    uint32_t a;
    asm("{ .reg .u64 t; cvta.to.shared.u64 t, %1; cvt.u32.u64 %0, t; }" : "=r"(a) : "l"(p));
    return a;
}
__device__ __forceinline__ void cp16(void* sdst, const void* gsrc) {
    asm volatile("cp.async.cg.shared.global [%0], [%1], 16;"
                 :: "r"(smem_u32(sdst)), "l"(gsrc));
}
#define CP_COMMIT() asm volatile("cp.async.commit_group;" ::: "memory")
#define CP_WAIT0()  asm volatile("cp.async.wait_group 0;" ::: "memory")

__device__ __forceinline__ void mma16816(float* c, uint32_t a0, uint32_t a1,
                                         uint32_t a2, uint32_t a3,
                                         uint32_t b0, uint32_t b1) {
    asm volatile(
        "mma.sync.aligned.m16n8k16.row.col.f32.f16.f16.f32 "
        "{%0,%1,%2,%3},{%4,%5,%6,%7},{%8,%9},{%0,%1,%2,%3};"
        : "+f"(c[0]), "+f"(c[1]), "+f"(c[2]), "+f"(c[3])
        : "r"(a0), "r"(a1), "r"(a2), "r"(a3), "r"(b0), "r"(b1));
}
__device__ __forceinline__ uint32_t packh(float x, float y) {
    __half2 p = __floats2half2_rn(x, y);
    return *reinterpret_cast<uint32_t*>(&p);
}

// =============== prep: weights -> fp16 SMEM-image chunks (R9 layout) ===============
__global__ void prep_weights(const float* __restrict__ Wq, const float* __restrict__ Wk,
                             const float* __restrict__ Wv) {
    int idx = blockIdx.x * 256 + threadIdx.x;   // 81920
    int chunk = idx >> 13;
    int n = (idx >> 8) & 31;
    int k = idx & 255;
    float w;
    if (chunk == 0)      w = Wq[k * 32 + n];
    else if (chunk == 1) w = Wk[k * 32 + n];
    else                 w = Wv[k * 256 + (chunk - 2) * 32 + n];
    unsigned off = (unsigned)chunk * WCHUNK + (unsigned)n * XSTR + (unsigned)kslot(k) * 2;
    *(__half*)(g_wimg + off) = __float2half(w);
}

// =============== main: one CTA (8 warps) per (b,h) group, 2 CTAs/SM ===============
__global__ __launch_bounds__(NTHR, 2)
void attn_mma_kernel(const float* __restrict__ X,
                     const float* __restrict__ bq, const float* __restrict__ bk,
                     const float* __restrict__ bv, float* __restrict__ out) {
    extern __shared__ unsigned char sm[];
    const int t = threadIdx.x, w = t >> 5, lane = t & 31;
    const int q = lane & 3, lq = lane >> 2;
    const int R = w * 16;
    const long long g = blockIdx.x;
    const float* Xg = X + g * 32768LL;
    float* Og = out + g * 32768LL;

    // issue Wq -> WB0, Wk -> WB1
    for (int i = t; i < WCHUNK / 16; i += NTHR) {
        cp16(sm + WB0 + i * 16, g_wimg + i * 16);
        cp16(sm + WB1 + i * 16, g_wimg + WCHUNK + i * 16);
    }
    CP_COMMIT();

    // ---- build X frag image from COALESCED float4 gmem reads ----
    // image: addr = wq*8192 + kt*512 + (slot ^ (kt&7))*16 + word*4
    //   slot = (row&7)*4 + q;  word = hi*2 + ((row>>3)&1)
    {
        const float4* X4 = (const float4*)Xg;
        #pragma unroll 4
        for (int i = t; i < 8192; i += NTHR) {
            int row = i >> 6, k0 = (i & 63) * 4;
            float4 f = X4[i];
            int wq = row >> 4;
            int slot0 = (row & 7) * 4 + ((k0 & 7) >> 1);     // q0 = (k0&7)>>1 in {0,2}
            int kt = k0 >> 4;
            int word = ((k0 >> 3) & 1) * 2 + ((row >> 3) & 1);
            unsigned base = (unsigned)(wq * 8192 + kt * 512 + word * 4);
            int sw = kt & 7;
            *(uint32_t*)(sm + base + (unsigned)((slot0 ^ sw) * 16))       = packh(f.x, f.y);
            *(uint32_t*)(sm + base + (unsigned)(((slot0 + 1) ^ sw) * 16)) = packh(f.z, f.w);
        }
    }
    CP_WAIT0();
    __syncthreads();   // [S0] X image built; Wq/Wk visible

    // ---- one-time: load this warp's 16 A-fragments into registers ----
    uint4 Xa[16];
    #pragma unroll
    for (int kt = 0; kt < 16; kt++)
        Xa[kt] = *(const uint4*)(sm + (unsigned)(w * 8192 + kt * 512 +
                                                 ((lane ^ (kt & 7)) * 16)));

    // ---------------- fused Q + K projection (A from regs) ----------------
    float Cq[4][4], Ck[4][4];
    #pragma unroll
    for (int n = 0; n < 4; n++) {
        Cq[n][0] = Cq[n][1] = Cq[n][2] = Cq[n][3] = 0.f;
        Ck[n][0] = Ck[n][1] = Ck[n][2] = Ck[n][3] = 0.f;
    }
    #pragma unroll 4
    for (int kt = 0; kt < 16; kt++) {
        unsigned ko = kt * 32 + q * 8;
        #pragma unroll
        for (int nt = 0; nt < 4; nt++) {
            uint2 bqf = *(const uint2*)(sm + WB0 + (unsigned)(nt * 8 + lq) * XSTR + ko);
            uint2 bkf = *(const uint2*)(sm + WB1 + (unsigned)(nt * 8 + lq) * XSTR + ko);
            mma16816(Cq[nt], Xa[kt].x, Xa[kt].y, Xa[kt].z, Xa[kt].w, bqf.x, bqf.y);
            mma16816(Ck[nt], Xa[kt].x, Xa[kt].y, Xa[kt].z, Xa[kt].w, bkf.x, bkf.y);
        }
    }
    // +bq, repack into scores A-fragments
    uint32_t qh[2][4];
    #pragma unroll
    for (int nt = 0; nt < 4; nt++) {
        float2 bb = *(const float2*)(bq + nt * 8 + 2 * q);
        Cq[nt][0] += bb.x; Cq[nt][1] += bb.y; Cq[nt][2] += bb.x; Cq[nt][3] += bb.y;
    }
    #pragma unroll
    for (int kt = 0; kt < 2; kt++) {
        qh[kt][0] = packh(Cq[2*kt][0],   Cq[2*kt][1]);
        qh[kt][1] = packh(Cq[2*kt][2],   Cq[2*kt][3]);
        qh[kt][2] = packh(Cq[2*kt+1][0], Cq[2*kt+1][1]);
        qh[kt][3] = packh(Cq[2*kt+1][2], Cq[2*kt+1][3]);
    }
    // write K image (+bk)
    #pragma unroll
    for (int nt = 0; nt < 4; nt++) {
        float2 bb = *(const float2*)(bk + nt * 8 + 2 * q);
        float c0 = Ck[nt][0] + bb.x, c1 = Ck[nt][1] + bb.y;
        float c2 = Ck[nt][2] + bb.x, c3 = Ck[nt][3] + bb.y;
        int p = kslot(nt * 8 + 2 * q) * 2;
        *(uint32_t*)(sm + K_OFF + (unsigned)(R + lq) * KSTR + p)     = packh(c0, c1);
        *(uint32_t*)(sm + K_OFF + (unsigned)(R + lq + 8) * KSTR + p) = packh(c2, c3);
    }
    __syncthreads();   // [S1] proj reads of WB done; K visible; all Xa loads done

    // issue Wv0 -> WB0
    for (int i = t; i < WCHUNK / 16; i += NTHR)
        cp16(sm + WB0 + i * 16, g_wimg + 2 * WCHUNK + i * 16);
    CP_COMMIT();

    // V-transpose constants (frag-major VT mapping, R12/R14-verified)
    const bool oddlq = (lq & 1);
    const unsigned vslotbase = (unsigned)((2 * q + (oddlq ? 1 : 0)) * 4 + (lq >> 1)) * 8;

    // ---------------- Vproj phase: 8 chunks, A from regs, 1 sync/chunk ----------
    // VT images overwrite the (now dead) X image region: all warps loaded Xa
    // before S1, and the first VT store happens after the c=0 sync below.
    #pragma unroll 1
    for (int c = 0; c < 8; c++) {
        CP_WAIT0();
        __syncthreads();   // Wv(c) visible; all warps done reading buf(c-1)
        if (c < 7) {
            unsigned dst = ((c + 1) & 1) ? WB1 : WB0;
            const unsigned char* src = g_wimg + (unsigned)(c + 3) * WCHUNK;
            for (int i = t; i < WCHUNK / 16; i += NTHR) cp16(sm + dst + i * 16, src + i * 16);
            CP_COMMIT();
        }
        const unsigned buf = (c & 1) ? WB1 : WB0;
        float Cv[4][4];
        #pragma unroll
        for (int n = 0; n < 4; n++) { Cv[n][0] = Cv[n][1] = Cv[n][2] = Cv[n][3] = 0.f; }
        #pragma unroll 4
        for (int kt = 0; kt < 16; kt++) {
            unsigned ko = kt * 32 + q * 8;
            #pragma unroll
            for (int nt = 0; nt < 4; nt++) {
                uint2 bf = *(const uint2*)(sm + buf + (unsigned)(nt * 8 + lq) * XSTR + ko);
                mma16816(Cv[nt], Xa[kt].x, Xa[kt].y, Xa[kt].z, Xa[kt].w, bf.x, bf.y);
            }
        }
        // VT(c) store: shfl pair-exchange -> frag-major image (warp w = frag kt=w)
        const unsigned vtw = VT_BASE + (unsigned)c * 8192;
        #pragma unroll
        for (int nt = 0; nt < 4; nt++) {
            float v0 = Cv[nt][0], v1 = Cv[nt][1], v2 = Cv[nt][2], v3 = Cv[nt][3];
            float sendA = oddlq ? v0 : v1;
            float recvA = __shfl_xor_sync(0xffffffffu, sendA, 4);
            float sendB = oddlq ? v2 : v3;
            float recvB = __shfl_xor_sync(0xffffffffu, sendB, 4);
            float a0 = oddlq ? recvA : v0, a1 = oddlq ? v1 : recvA;
            float b0 = oddlq ? recvB : v2, b1 = oddlq ? v3 : recvB;
            unsigned fb = vtw + (unsigned)(w * 4 + nt) * 256 + vslotbase;
            *(uint32_t*)(sm + fb)     = packh(a0, a1);
            *(uint32_t*)(sm + fb + 4) = packh(b0, b1);
        }
    }
    __syncthreads();   // [S10] all VT images visible

    // ---------------- scores S = Q @ K^T ----------------
    float Cs[16][4];
    #pragma unroll
    for (int n = 0; n < 16; n++) { Cs[n][0] = Cs[n][1] = Cs[n][2] = Cs[n][3] = 0.f; }
    #pragma unroll
    for (int ng = 0; ng < 4; ng++) {
        #pragma unroll
        for (int kt = 0; kt < 2; kt++) {
            unsigned ko = kt * 32 + q * 8;
            #pragma unroll
            for (int ni = 0; ni < 4; ni++) {
                int nt = ng * 4 + ni;
                uint2 bh = *(const uint2*)(sm + K_OFF + (unsigned)(nt * 8 + lq) * KSTR + ko);
                mma16816(Cs[nt], qh[kt][0], qh[kt][1], qh[kt][2], qh[kt][3], bh.x, bh.y);
            }
        }
    }

    // ---------------- softmax (registers + quad shuffles) ----------------
    {
        float m0 = -1e30f, m1 = -1e30f;
        #pragma unroll
        for (int nt = 0; nt < 16; nt++) {
            m0 = fmaxf(m0, fmaxf(Cs[nt][0], Cs[nt][1]));
            m1 = fmaxf(m1, fmaxf(Cs[nt][2], Cs[nt][3]));
        }
        m0 = fmaxf(m0, __shfl_xor_sync(0xffffffffu, m0, 1));
        m0 = fmaxf(m0, __shfl_xor_sync(0xffffffffu, m0, 2));
        m1 = fmaxf(m1, __shfl_xor_sync(0xffffffffu, m1, 1));
        m1 = fmaxf(m1, __shfl_xor_sync(0xffffffffu, m1, 2));
        float s0 = 0.f, s1 = 0.f;
        #pragma unroll
        for (int nt = 0; nt < 16; nt++) {
            Cs[nt][0] = __expf(Cs[nt][0] - m0); Cs[nt][1] = __expf(Cs[nt][1] - m0);
            Cs[nt][2] = __expf(Cs[nt][2] - m1); Cs[nt][3] = __expf(Cs[nt][3] - m1);
            s0 += Cs[nt][0] + Cs[nt][1];
            s1 += Cs[nt][2] + Cs[nt][3];
        }
        s0 += __shfl_xor_sync(0xffffffffu, s0, 1);
        s0 += __shfl_xor_sync(0xffffffffu, s0, 2);
        s1 += __shfl_xor_sync(0xffffffffu, s1, 1);
        s1 += __shfl_xor_sync(0xffffffffu, s1, 2);
        const float i0 = 1.f / s0, i1 = 1.f / s1;
        #pragma unroll
        for (int nt = 0; nt < 16; nt++) {
            Cs[nt][0] *= i0; Cs[nt][1] *= i0; Cs[nt][2] *= i1; Cs[nt][3] *= i1;
        }
    }
    // attn A-frags
    uint32_t ah[8][4];
    #pragma unroll
    for (int kt = 0; kt < 8; kt++) {
        ah[kt][0] = packh(Cs[2*kt][0],   Cs[2*kt][1]);
        ah[kt][1] = packh(Cs[2*kt][2],   Cs[2*kt][3]);
        ah[kt][2] = packh(Cs[2*kt+1][0], Cs[2*kt+1][1]);
        ah[kt][3] = packh(Cs[2*kt+1][2], Cs[2*kt+1][3]);
    }

    // ---------------- AV phase: 8 chunks, ZERO barriers ----------------
    const unsigned lko8 = (unsigned)lane * 8;
    #pragma unroll 1
    for (int c = 0; c < 8; c++) {
        const unsigned vt = VT_BASE + (unsigned)c * 8192;
        float Co[4][4];
        #pragma unroll
        for (int n = 0; n < 4; n++) { Co[n][0] = Co[n][1] = Co[n][2] = Co[n][3] = 0.f; }
        #pragma unroll
        for (int kt = 0; kt < 8; kt++) {
            #pragma unroll
            for (int nt = 0; nt < 4; nt++) {
                uint2 bh = *(const uint2*)(sm + vt + (unsigned)(kt * 4 + nt) * 256 + lko8);
                mma16816(Co[nt], ah[kt][0], ah[kt][1], ah[kt][2], ah[kt][3], bh.x, bh.y);
            }
        }
        #pragma unroll
        for (int nt = 0; nt < 4; nt++) {
            int col = c * 32 + nt * 8 + 2 * q;
            float2 bb = *(const float2*)(bv + col);
            *(float2*)(Og + (long long)(R + lq) * 256 + col) =
                make_float2(Co[nt][0] + bb.x, Co[nt][1] + bb.y);
            *(float2*)(Og + (long long)(R + 8 + lq) * 256 + col) =
                make_float2(Co[nt][2] + bb.x, Co[nt][3] + bb.y);
        }
    }
}

extern "C" void kernel_launch(void* const* d_in, const int* in_sizes, int n_in,
                              void* d_out, int out_size) {
    const float* X  = (const float*)d_in[0];
    const float* Wq = (const float*)d_in[1];
    const float* bq = (const float*)d_in[2];
    const float* Wk = (const float*)d_in[3];
    const float* bk = (const float*)d_in[4];
    const float* Wv = (const float*)d_in[5];
    const float* bv = (const float*)d_in[6];
    float* out = (float*)d_out;

    const int groups = in_sizes[0] / (128 * 256);   // 2048

    prep_weights<<<320, 256>>>(Wq, Wk, Wv);

    cudaFuncSetAttribute(attn_mma_kernel,
                         cudaFuncAttributeMaxDynamicSharedMemorySize, SMEM_BYTES);
    attn_mma_kernel<<<groups, NTHR, SMEM_BYTES>>>(X, bq, bk, bv, out);
}

// round 16
// speedup vs baseline: 1.3449x; 1.1541x over previous
#include <cuda_runtime.h>
#include <cuda_fp16.h>
#include <cstdint>

// B=16,H=128 -> 2048 groups; per group X[128,256], D=32.
#define NTHR 256

// ---------------- SMEM layout (bytes), plain-k images, LDSM-friendly strides ----
#define XP_OFF  0                    // X fp16 [128][XSTR] = 67,584
#define XSTR    528                  // 528 mod 128 = 16 -> 8-row LDSM conflict-free
#define WB0     67584                // weight buffer 0 (16,896)
#define WCHUNK  16896                // 32 rows x XSTR
#define WB1     84480                // weight buffer 1 / K overlay
#define K_OFF   84480                // K image [128][112] = 14,336
#define KSTR    112
#define VT_OFF  101376               // V^T chunk [32][272] = 8,704
#define VSTR    272
#define SMEM_BYTES 110080            // -> 2 CTAs/SM

// 10 weight-chunk images: 0=Wq, 1=Wk, 2..9=Wv col-chunks of 32 (row n, plain k)
__device__ __align__(16) unsigned char g_wimg[10 * WCHUNK];

__device__ __forceinline__ uint32_t smem_u32(const void* p) {
    uint32_t a;
    asm("{ .reg .u64 t; cvta.to.shared.u64 t, %1; cvt.u32.u64 %0, t; }" : "=r"(a) : "l"(p));
    return a;
}
__device__ __forceinline__ void cp16(void* sdst, const void* gsrc) {
    asm volatile("cp.async.cg.shared.global [%0], [%1], 16;"
                 :: "r"(smem_u32(sdst)), "l"(gsrc));
}
#define CP_COMMIT() asm volatile("cp.async.commit_group;" ::: "memory")
#define CP_WAIT0()  asm volatile("cp.async.wait_group 0;" ::: "memory")

__device__ __forceinline__ void mma16816(float* c, uint32_t a0, uint32_t a1,
                                         uint32_t a2, uint32_t a3,
                                         uint32_t b0, uint32_t b1) {
    asm volatile(
        "mma.sync.aligned.m16n8k16.row.col.f32.f16.f16.f32 "
        "{%0,%1,%2,%3},{%4,%5,%6,%7},{%8,%9},{%0,%1,%2,%3};"
        : "+f"(c[0]), "+f"(c[1]), "+f"(c[2]), "+f"(c[3])
        : "r"(a0), "r"(a1), "r"(a2), "r"(a3), "r"(b0), "r"(b1));
}
__device__ __forceinline__ uint4 ldsm_x4(uint32_t addr) {
    uint4 r;
    asm volatile("ldmatrix.sync.aligned.m8n8.x4.shared.b16 {%0,%1,%2,%3}, [%4];"
                 : "=r"(r.x), "=r"(r.y), "=r"(r.z), "=r"(r.w) : "r"(addr));
    return r;
}
__device__ __forceinline__ uint32_t packh(float x, float y) {
    __half2 p = __floats2half2_rn(x, y);
    return *reinterpret_cast<uint32_t*>(&p);
}

// =============== prep: weights -> fp16 plain-k SMEM-image chunks ===============
__global__ void prep_weights(const float* __restrict__ Wq, const float* __restrict__ Wk,
                             const float* __restrict__ Wv) {
    int idx = blockIdx.x * 256 + threadIdx.x;   // 81920
    int chunk = idx >> 13;
    int n = (idx >> 8) & 31;
    int k = idx & 255;
    float w;
    if (chunk == 0)      w = Wq[k * 32 + n];
    else if (chunk == 1) w = Wk[k * 32 + n];
    else                 w = Wv[k * 256 + (chunk - 2) * 32 + n];
    *(__half*)(g_wimg + (unsigned)chunk * WCHUNK + (unsigned)n * XSTR + (unsigned)k * 2)
        = __float2half(w);
}

// =============== main: one CTA (8 warps) per (b,h) group, 2 CTAs/SM ===============
__global__ __launch_bounds__(NTHR, 2)
void attn_mma_kernel(const float* __restrict__ X,
                     const float* __restrict__ bq, const float* __restrict__ bk,
                     const float* __restrict__ bv, float* __restrict__ out) {
    extern __shared__ unsigned char sm[];
    const uint32_t sb = smem_u32(sm);
    const int t = threadIdx.x, w = t >> 5, lane = t & 31;
    const int q = lane & 3, lq = lane >> 2;
    const int R = w * 16;
    const long long g = blockIdx.x;
    const float* Xg = X + g * 32768LL;
    float* Og = out + g * 32768LL;

    // LDSM per-lane row/col selectors
    const int lm  = lane >> 3;            // matrix index 0..3
    const int li  = lane & 7;             // row within matrix
    // A x4: m0=rows 0-7 klo, m1=rows 8-15 klo, m2=rows 0-7 khi, m3=rows 8-15 khi
    const uint32_t aRow = (unsigned)(R + ((lm & 1) ? 8 : 0) + li);
    const uint32_t aSel = aRow * XSTR + (unsigned)((lm >> 1) * 16);
    // B x4 (stride S): m0=nt0 rows klo, m1=nt0 khi, m2=nt1 rows klo, m3=nt1 khi
    const uint32_t bRow = (unsigned)((lm >> 1) * 8 + li);   // + ntp*16 at use
    const uint32_t bSelX = bRow * XSTR + (unsigned)((lm & 1) * 16);
    const uint32_t bSelK = bRow * KSTR + (unsigned)((lm & 1) * 16);
    const uint32_t bSelV = bRow * VSTR + (unsigned)((lm & 1) * 16);

    // issue Wq -> WB0, Wk -> WB1
    for (int i = t; i < WCHUNK / 16; i += NTHR) {
        cp16(sm + WB0 + i * 16, g_wimg + i * 16);
        cp16(sm + WB1 + i * 16, g_wimg + WCHUNK + i * 16);
    }
    CP_COMMIT();

    // X load -> plain fp16 image (coalesced float4 reads, STS.64 writes)
    {
        const float4* X4 = (const float4*)Xg;
        #pragma unroll 4
        for (int i = t; i < 8192; i += NTHR) {
            int row = i >> 6, k0 = (i & 63) * 4;
            float4 f = X4[i];
            uint2 v = make_uint2(packh(f.x, f.y), packh(f.z, f.w));
            *(uint2*)(sm + XP_OFF + (unsigned)row * XSTR + (unsigned)k0 * 2) = v;
        }
    }
    CP_WAIT0();
    __syncthreads();   // [S0] X image + Wq/Wk visible

    // ---------------- fused Q + K projection ----------------
    float Cq[4][4], Ck[4][4];
    #pragma unroll
    for (int n = 0; n < 4; n++) {
        Cq[n][0] = Cq[n][1] = Cq[n][2] = Cq[n][3] = 0.f;
        Ck[n][0] = Ck[n][1] = Ck[n][2] = Ck[n][3] = 0.f;
    }
    #pragma unroll 4
    for (int kt = 0; kt < 16; kt++) {
        uint4 A = ldsm_x4(sb + XP_OFF + aSel + kt * 32);
        #pragma unroll
        for (int ntp = 0; ntp < 2; ntp++) {
            uint4 BQ = ldsm_x4(sb + WB0 + bSelX + (unsigned)(ntp * 16) * XSTR + kt * 32);
            uint4 BK = ldsm_x4(sb + WB1 + bSelX + (unsigned)(ntp * 16) * XSTR + kt * 32);
            mma16816(Cq[2 * ntp],     A.x, A.y, A.z, A.w, BQ.x, BQ.y);
            mma16816(Cq[2 * ntp + 1], A.x, A.y, A.z, A.w, BQ.z, BQ.w);
            mma16816(Ck[2 * ntp],     A.x, A.y, A.z, A.w, BK.x, BK.y);
            mma16816(Ck[2 * ntp + 1], A.x, A.y, A.z, A.w, BK.z, BK.w);
        }
    }
    // +bq, repack into scores A-fragments
    uint32_t qh[2][4];
    #pragma unroll
    for (int nt = 0; nt < 4; nt++) {
        float2 bb = *(const float2*)(bq + nt * 8 + 2 * q);
        Cq[nt][0] += bb.x; Cq[nt][1] += bb.y; Cq[nt][2] += bb.x; Cq[nt][3] += bb.y;
    }
    #pragma unroll
    for (int kt = 0; kt < 2; kt++) {
        qh[kt][0] = packh(Cq[2*kt][0],   Cq[2*kt][1]);
        qh[kt][1] = packh(Cq[2*kt][2],   Cq[2*kt][3]);
        qh[kt][2] = packh(Cq[2*kt+1][0], Cq[2*kt+1][1]);
        qh[kt][3] = packh(Cq[2*kt+1][2], Cq[2*kt+1][3]);
    }
    __syncthreads();   // [S1] proj reads of WB0/WB1 done

    // write K image (+bk), plain layout: row=token, col=d*2
    #pragma unroll
    for (int nt = 0; nt < 4; nt++) {
        float2 bb = *(const float2*)(bk + nt * 8 + 2 * q);
        unsigned dcol = (unsigned)(nt * 8 + 2 * q) * 2;
        *(uint32_t*)(sm + K_OFF + (unsigned)(R + lq) * KSTR + dcol) =
            packh(Ck[nt][0] + bb.x, Ck[nt][1] + bb.y);
        *(uint32_t*)(sm + K_OFF + (unsigned)(R + lq + 8) * KSTR + dcol) =
            packh(Ck[nt][2] + bb.x, Ck[nt][3] + bb.y);
    }
    __syncthreads();   // [S2] K visible

    // issue Wv chunk 0 -> WB0
    for (int i = t; i < WCHUNK / 16; i += NTHR)
        cp16(sm + WB0 + i * 16, g_wimg + 2 * WCHUNK + i * 16);
    CP_COMMIT();

    // ---------------- scores S = Q @ K^T ----------------
    float Cs[16][4];
    #pragma unroll
    for (int n = 0; n < 16; n++) { Cs[n][0] = Cs[n][1] = Cs[n][2] = Cs[n][3] = 0.f; }
    #pragma unroll
    for (int ntp = 0; ntp < 8; ntp++) {
        #pragma unroll
        for (int kt = 0; kt < 2; kt++) {
            uint4 BK = ldsm_x4(sb + K_OFF + bSelK + (unsigned)(ntp * 16) * KSTR + kt * 32);
            mma16816(Cs[2 * ntp],     qh[kt][0], qh[kt][1], qh[kt][2], qh[kt][3], BK.x, BK.y);
            mma16816(Cs[2 * ntp + 1], qh[kt][0], qh[kt][1], qh[kt][2], qh[kt][3], BK.z, BK.w);
        }
    }

    // ---------------- softmax (registers + quad shuffles) ----------------
    {
        float m0 = -1e30f, m1 = -1e30f;
        #pragma unroll
        for (int nt = 0; nt < 16; nt++) {
            m0 = fmaxf(m0, fmaxf(Cs[nt][0], Cs[nt][1]));
            m1 = fmaxf(m1, fmaxf(Cs[nt][2], Cs[nt][3]));
        }
        m0 = fmaxf(m0, __shfl_xor_sync(0xffffffffu, m0, 1));
        m0 = fmaxf(m0, __shfl_xor_sync(0xffffffffu, m0, 2));
        m1 = fmaxf(m1, __shfl_xor_sync(0xffffffffu, m1, 1));
        m1 = fmaxf(m1, __shfl_xor_sync(0xffffffffu, m1, 2));
        float s0 = 0.f, s1 = 0.f;
        #pragma unroll
        for (int nt = 0; nt < 16; nt++) {
            Cs[nt][0] = __expf(Cs[nt][0] - m0); Cs[nt][1] = __expf(Cs[nt][1] - m0);
            Cs[nt][2] = __expf(Cs[nt][2] - m1); Cs[nt][3] = __expf(Cs[nt][3] - m1);
            s0 += Cs[nt][0] + Cs[nt][1];
            s1 += Cs[nt][2] + Cs[nt][3];
        }
        s0 += __shfl_xor_sync(0xffffffffu, s0, 1);
        s0 += __shfl_xor_sync(0xffffffffu, s0, 2);
        s1 += __shfl_xor_sync(0xffffffffu, s1, 1);
        s1 += __shfl_xor_sync(0xffffffffu, s1, 2);
        const float i0 = 1.f / s0, i1 = 1.f / s1;
        #pragma unroll
        for (int nt = 0; nt < 16; nt++) {
            Cs[nt][0] *= i0; Cs[nt][1] *= i0; Cs[nt][2] *= i1; Cs[nt][3] *= i1;
        }
    }
    // attn A-frags
    uint32_t ah[8][4];
    #pragma unroll
    for (int kt = 0; kt < 8; kt++) {
        ah[kt][0] = packh(Cs[2*kt][0],   Cs[2*kt][1]);
        ah[kt][1] = packh(Cs[2*kt][2],   Cs[2*kt][3]);
        ah[kt][2] = packh(Cs[2*kt+1][0], Cs[2*kt+1][1]);
        ah[kt][3] = packh(Cs[2*kt+1][2], Cs[2*kt+1][3]);
    }

    // V-transpose constants (plain token layout)
    const int j2 = 2 * (lq >> 1);
    const bool oddlq = (lq & 1);

    // ---------------- 8 output-column chunks of 32 (R9 structure) ----------------
    #pragma unroll 1
    for (int c = 0; c < 8; c++) {
        const unsigned buf = (c & 1) ? WB1 : WB0;
        CP_WAIT0();
        __syncthreads();   // chunk weights ready; prev-iter VT reads done
        if (c < 7) {
            unsigned dst = (c & 1) ? WB0 : WB1;
            const unsigned char* src = g_wimg + (unsigned)(c + 3) * WCHUNK;
            for (int i = t; i < WCHUNK / 16; i += NTHR) cp16(sm + dst + i * 16, src + i * 16);
            CP_COMMIT();
        }

        // V chunk = X @ Wv[:, c*32 .. c*32+31]
        float Cv[4][4];
        #pragma unroll
        for (int n = 0; n < 4; n++) { Cv[n][0] = Cv[n][1] = Cv[n][2] = Cv[n][3] = 0.f; }
        #pragma unroll 4
        for (int kt = 0; kt < 16; kt++) {
            uint4 A = ldsm_x4(sb + XP_OFF + aSel + kt * 32);
            #pragma unroll
            for (int ntp = 0; ntp < 2; ntp++) {
                uint4 B = ldsm_x4(sb + buf + bSelX + (unsigned)(ntp * 16) * XSTR + kt * 32);
                mma16816(Cv[2 * ntp],     A.x, A.y, A.z, A.w, B.x, B.y);
                mma16816(Cv[2 * ntp + 1], A.x, A.y, A.z, A.w, B.z, B.w);
            }
        }
        // transpose-store V chunk: shfl.xor(4) pair exchange -> plain [col][token]
        #pragma unroll
        for (int nt = 0; nt < 4; nt++) {
            float v0 = Cv[nt][0], v1 = Cv[nt][1], v2 = Cv[nt][2], v3 = Cv[nt][3];
            float sendA = oddlq ? v0 : v1;
            float recvA = __shfl_xor_sync(0xffffffffu, sendA, 4);
            float sendB = oddlq ? v2 : v3;
            float recvB = __shfl_xor_sync(0xffffffffu, sendB, 4);
            float a0 = oddlq ? recvA : v0, a1 = oddlq ? v1 : recvA;   // tokens R+j2, +1
            float b0 = oddlq ? recvB : v2, b1 = oddlq ? v3 : recvB;   // tokens R+8+j2, +1
            unsigned cc = (unsigned)(nt * 8 + 2 * q + (oddlq ? 1 : 0)) * VSTR;
            *(uint32_t*)(sm + VT_OFF + cc + (unsigned)(R + j2) * 2)     = packh(a0, a1);
            *(uint32_t*)(sm + VT_OFF + cc + (unsigned)(R + 8 + j2) * 2) = packh(b0, b1);
        }
        __syncthreads();

        // O chunk = attn @ V
        float Co[4][4];
        #pragma unroll
        for (int n = 0; n < 4; n++) { Co[n][0] = Co[n][1] = Co[n][2] = Co[n][3] = 0.f; }
        #pragma unroll
        for (int kt = 0; kt < 8; kt++) {
            #pragma unroll
            for (int ntp = 0; ntp < 2; ntp++) {
                uint4 B = ldsm_x4(sb + VT_OFF + bSelV + (unsigned)(ntp * 16) * VSTR + kt * 32);
                mma16816(Co[2 * ntp],     ah[kt][0], ah[kt][1], ah[kt][2], ah[kt][3], B.x, B.y);
                mma16816(Co[2 * ntp + 1], ah[kt][0], ah[kt][1], ah[kt][2], ah[kt][3], B.z, B.w);
            }
        }
        // epilogue: +bv, store (softmax rows sum to 1 -> bias adds directly)
        #pragma unroll
        for (int nt = 0; nt < 4; nt++) {
            int col = c * 32 + nt * 8 + 2 * q;
            float2 bb = *(const float2*)(bv + col);
            *(float2*)(Og + (long long)(R + lq) * 256 + col) =
                make_float2(Co[nt][0] + bb.x, Co[nt][1] + bb.y);
            *(float2*)(Og + (long long)(R + 8 + lq) * 256 + col) =
                make_float2(Co[nt][2] + bb.x, Co[nt][3] + bb.y);
        }
    }
}

extern "C" void kernel_launch(void* const* d_in, const int* in_sizes, int n_in,
                              void* d_out, int out_size) {
    const float* X  = (const float*)d_in[0];
    const float* Wq = (const float*)d_in[1];
    const float* bq = (const float*)d_in[2];
    const float* Wk = (const float*)d_in[3];
    const float* bk = (const float*)d_in[4];
    const float* Wv = (const float*)d_in[5];
    const float* bv = (const float*)d_in[6];
    float* out = (float*)d_out;

    const int groups = in_sizes[0] / (128 * 256);   // 2048

    prep_weights<<<320, 256>>>(Wq, Wk, Wv);

    cudaFuncSetAttribute(attn_mma_kernel,
                         cudaFuncAttributeMaxDynamicSharedMemorySize, SMEM_BYTES);
    attn_mma_kernel<<<groups, NTHR, SMEM_BYTES>>>(X, bq, bk, bv, out);
}

// round 17
// speedup vs baseline: 1.4514x; 1.0792x over previous
#include <cuda_runtime.h>
#include <cuda_fp16.h>
#include <cstdint>

// B=16,H=128 -> 2048 groups; per group X[128,256], D=32.
#define NTHR 256

// ---------------- SMEM layout (bytes), plain-k images, LDSM-friendly strides ----
#define XP_OFF  0                    // X fp16 [128][XSTR] = 67,584
#define XSTR    528                  // 8-row LDSM conflict-free (20r mod 32 distinct)
#define WB0     67584                // weight buffer 0 (16,896)
#define WCHUNK  16896                // 32 rows x XSTR
#define WB1     84480                // weight buffer 1 (16,896)
#define K_OFF   101376               // K image [128][80] = 10,240 (own region)
#define KSTR    80
#define VT_OFF  101376               // V^T chunk [32][272] — overlays K after scores
#define VSTR    272
#define SMEM_BYTES 111616            // -> 2 CTAs/SM (limit 116,224)

// 10 weight-chunk images: 0=Wq, 1=Wk, 2..9=Wv col-chunks of 32 (row n, plain k)
__device__ __align__(16) unsigned char g_wimg[10 * WCHUNK];

__device__ __forceinline__ uint32_t smem_u32(const void* p) {
    uint32_t a;
    asm("{ .reg .u64 t; cvta.to.shared.u64 t, %1; cvt.u32.u64 %0, t; }" : "=r"(a) : "l"(p));
    return a;
}
__device__ __forceinline__ void cp16(void* sdst, const void* gsrc) {
    asm volatile("cp.async.cg.shared.global [%0], [%1], 16;"
                 :: "r"(smem_u32(sdst)), "l"(gsrc));
}
#define CP_COMMIT() asm volatile("cp.async.commit_group;" ::: "memory")
#define CP_WAIT0()  asm volatile("cp.async.wait_group 0;" ::: "memory")

__device__ __forceinline__ void mma16816(float* c, uint32_t a0, uint32_t a1,
                                         uint32_t a2, uint32_t a3,
                                         uint32_t b0, uint32_t b1) {
    asm volatile(
        "mma.sync.aligned.m16n8k16.row.col.f32.f16.f16.f32 "
        "{%0,%1,%2,%3},{%4,%5,%6,%7},{%8,%9},{%0,%1,%2,%3};"
        : "+f"(c[0]), "+f"(c[1]), "+f"(c[2]), "+f"(c[3])
        : "r"(a0), "r"(a1), "r"(a2), "r"(a3), "r"(b0), "r"(b1));
}
__device__ __forceinline__ uint4 ldsm_x4(uint32_t addr) {
    uint4 r;
    asm volatile("ldmatrix.sync.aligned.m8n8.x4.shared.b16 {%0,%1,%2,%3}, [%4];"
                 : "=r"(r.x), "=r"(r.y), "=r"(r.z), "=r"(r.w) : "r"(addr));
    return r;
}
__device__ __forceinline__ uint32_t packh(float x, float y) {
    __half2 p = __floats2half2_rn(x, y);
    return *reinterpret_cast<uint32_t*>(&p);
}

// =============== prep: weights -> fp16 plain-k SMEM-image chunks ===============
__global__ void prep_weights(const float* __restrict__ Wq, const float* __restrict__ Wk,
                             const float* __restrict__ Wv) {
    int idx = blockIdx.x * 256 + threadIdx.x;   // 81920
    int chunk = idx >> 13;
    int n = (idx >> 8) & 31;
    int k = idx & 255;
    float w;
    if (chunk == 0)      w = Wq[k * 32 + n];
    else if (chunk == 1) w = Wk[k * 32 + n];
    else                 w = Wv[k * 256 + (chunk - 2) * 32 + n];
    *(__half*)(g_wimg + (unsigned)chunk * WCHUNK + (unsigned)n * XSTR + (unsigned)k * 2)
        = __float2half(w);
}

// =============== main: one CTA (8 warps) per (b,h) group, 2 CTAs/SM ===============
__global__ __launch_bounds__(NTHR, 2)
void attn_mma_kernel(const float* __restrict__ X,
                     const float* __restrict__ bq, const float* __restrict__ bk,
                     const float* __restrict__ bv, float* __restrict__ out) {
    extern __shared__ unsigned char sm[];
    const uint32_t sb = smem_u32(sm);
    const int t = threadIdx.x, w = t >> 5, lane = t & 31;
    const int q = lane & 3, lq = lane >> 2;
    const int R = w * 16;
    const long long g = blockIdx.x;
    const float* Xg = X + g * 32768LL;
    float* Og = out + g * 32768LL;

    // LDSM per-lane row/col selectors
    const int lm  = lane >> 3;            // matrix index 0..3
    const int li  = lane & 7;             // row within matrix
    const uint32_t aRow = (unsigned)(R + ((lm & 1) ? 8 : 0) + li);
    const uint32_t aSel = aRow * XSTR + (unsigned)((lm >> 1) * 16);
    const uint32_t bRow = (unsigned)((lm >> 1) * 8 + li);   // + ntp*16 at use
    const uint32_t bSelX = bRow * XSTR + (unsigned)((lm & 1) * 16);
    const uint32_t bSelK = bRow * KSTR + (unsigned)((lm & 1) * 16);
    const uint32_t bSelV = bRow * VSTR + (unsigned)((lm & 1) * 16);

    // issue Wq -> WB0, Wk -> WB1
    for (int i = t; i < WCHUNK / 16; i += NTHR) {
        cp16(sm + WB0 + i * 16, g_wimg + i * 16);
        cp16(sm + WB1 + i * 16, g_wimg + WCHUNK + i * 16);
    }
    CP_COMMIT();

    // X load -> plain fp16 image (coalesced float4 reads, STS.64 writes)
    {
        const float4* X4 = (const float4*)Xg;
        #pragma unroll 4
        for (int i = t; i < 8192; i += NTHR) {
            int row = i >> 6, k0 = (i & 63) * 4;
            float4 f = X4[i];
            uint2 v = make_uint2(packh(f.x, f.y), packh(f.z, f.w));
            *(uint2*)(sm + XP_OFF + (unsigned)row * XSTR + (unsigned)k0 * 2) = v;
        }
    }
    CP_WAIT0();
    __syncthreads();   // [S0] X image + Wq/Wk visible

    // ---------------- fused Q + K projection ----------------
    float Cq[4][4], Ck[4][4];
    #pragma unroll
    for (int n = 0; n < 4; n++) {
        Cq[n][0] = Cq[n][1] = Cq[n][2] = Cq[n][3] = 0.f;
        Ck[n][0] = Ck[n][1] = Ck[n][2] = Ck[n][3] = 0.f;
    }
    #pragma unroll 4
    for (int kt = 0; kt < 16; kt++) {
        uint4 A = ldsm_x4(sb + XP_OFF + aSel + kt * 32);
        #pragma unroll
        for (int ntp = 0; ntp < 2; ntp++) {
            uint4 BQ = ldsm_x4(sb + WB0 + bSelX + (unsigned)(ntp * 16) * XSTR + kt * 32);
            uint4 BK = ldsm_x4(sb + WB1 + bSelX + (unsigned)(ntp * 16) * XSTR + kt * 32);
            mma16816(Cq[2 * ntp],     A.x, A.y, A.z, A.w, BQ.x, BQ.y);
            mma16816(Cq[2 * ntp + 1], A.x, A.y, A.z, A.w, BQ.z, BQ.w);
            mma16816(Ck[2 * ntp],     A.x, A.y, A.z, A.w, BK.x, BK.y);
            mma16816(Ck[2 * ntp + 1], A.x, A.y, A.z, A.w, BK.z, BK.w);
        }
    }
    // +bq, repack into scores A-fragments
    uint32_t qh[2][4];
    #pragma unroll
    for (int nt = 0; nt < 4; nt++) {
        float2 bb = *(const float2*)(bq + nt * 8 + 2 * q);
        Cq[nt][0] += bb.x; Cq[nt][1] += bb.y; Cq[nt][2] += bb.x; Cq[nt][3] += bb.y;
    }
    #pragma unroll
    for (int kt = 0; kt < 2; kt++) {
        qh[kt][0] = packh(Cq[2*kt][0],   Cq[2*kt][1]);
        qh[kt][1] = packh(Cq[2*kt][2],   Cq[2*kt][3]);
        qh[kt][2] = packh(Cq[2*kt+1][0], Cq[2*kt+1][1]);
        qh[kt][3] = packh(Cq[2*kt+1][2], Cq[2*kt+1][3]);
    }
    // write K image (+bk) into its own region (no WB overlay -> no hazard)
    #pragma unroll
    for (int nt = 0; nt < 4; nt++) {
        float2 bb = *(const float2*)(bk + nt * 8 + 2 * q);
        unsigned dcol = (unsigned)(nt * 8 + 2 * q) * 2;
        *(uint32_t*)(sm + K_OFF + (unsigned)(R + lq) * KSTR + dcol) =
            packh(Ck[nt][0] + bb.x, Ck[nt][1] + bb.y);
        *(uint32_t*)(sm + K_OFF + (unsigned)(R + lq + 8) * KSTR + dcol) =
            packh(Ck[nt][2] + bb.x, Ck[nt][3] + bb.y);
    }
    __syncthreads();   // [S1] proj reads of WB0/WB1 done; K visible

    // issue Wv0 -> WB0 AND Wv1 -> WB1 (pair 0)
    for (int i = t; i < WCHUNK / 16; i += NTHR) {
        cp16(sm + WB0 + i * 16, g_wimg + 2 * WCHUNK + i * 16);
        cp16(sm + WB1 + i * 16, g_wimg + 3 * WCHUNK + i * 16);
    }
    CP_COMMIT();

    // ---------------- scores S = Q @ K^T ----------------
    float Cs[16][4];
    #pragma unroll
    for (int n = 0; n < 16; n++) { Cs[n][0] = Cs[n][1] = Cs[n][2] = Cs[n][3] = 0.f; }
    #pragma unroll
    for (int ntp = 0; ntp < 8; ntp++) {
        #pragma unroll
        for (int kt = 0; kt < 2; kt++) {
            uint4 BK = ldsm_x4(sb + K_OFF + bSelK + (unsigned)(ntp * 16) * KSTR + kt * 32);
            mma16816(Cs[2 * ntp],     qh[kt][0], qh[kt][1], qh[kt][2], qh[kt][3], BK.x, BK.y);
            mma16816(Cs[2 * ntp + 1], qh[kt][0], qh[kt][1], qh[kt][2], qh[kt][3], BK.z, BK.w);
        }
    }

    // ---------------- softmax (registers + quad shuffles) ----------------
    {
        float m0 = -1e30f, m1 = -1e30f;
        #pragma unroll
        for (int nt = 0; nt < 16; nt++) {
            m0 = fmaxf(m0, fmaxf(Cs[nt][0], Cs[nt][1]));
            m1 = fmaxf(m1, fmaxf(Cs[nt][2], Cs[nt][3]));
        }
        m0 = fmaxf(m0, __shfl_xor_sync(0xffffffffu, m0, 1));
        m0 = fmaxf(m0, __shfl_xor_sync(0xffffffffu, m0, 2));
        m1 = fmaxf(m1, __shfl_xor_sync(0xffffffffu, m1, 1));
        m1 = fmaxf(m1, __shfl_xor_sync(0xffffffffu, m1, 2));
        float s0 = 0.f, s1 = 0.f;
        #pragma unroll
        for (int nt = 0; nt < 16; nt++) {
            Cs[nt][0] = __expf(Cs[nt][0] - m0); Cs[nt][1] = __expf(Cs[nt][1] - m0);
            Cs[nt][2] = __expf(Cs[nt][2] - m1); Cs[nt][3] = __expf(Cs[nt][3] - m1);
            s0 += Cs[nt][0] + Cs[nt][1];
            s1 += Cs[nt][2] + Cs[nt][3];
        }
        s0 += __shfl_xor_sync(0xffffffffu, s0, 1);
        s0 += __shfl_xor_sync(0xffffffffu, s0, 2);
        s1 += __shfl_xor_sync(0xffffffffu, s1, 1);
        s1 += __shfl_xor_sync(0xffffffffu, s1, 2);
        const float i0 = 1.f / s0, i1 = 1.f / s1;
        #pragma unroll
        for (int nt = 0; nt < 16; nt++) {
            Cs[nt][0] *= i0; Cs[nt][1] *= i0; Cs[nt][2] *= i1; Cs[nt][3] *= i1;
        }
    }
    // attn A-frags
    uint32_t ah[8][4];
    #pragma unroll
    for (int kt = 0; kt < 8; kt++) {
        ah[kt][0] = packh(Cs[2*kt][0],   Cs[2*kt][1]);
        ah[kt][1] = packh(Cs[2*kt][2],   Cs[2*kt][3]);
        ah[kt][2] = packh(Cs[2*kt+1][0], Cs[2*kt+1][1]);
        ah[kt][3] = packh(Cs[2*kt+1][2], Cs[2*kt+1][3]);
    }

    // V-transpose constants (plain token layout)
    const int j2 = 2 * (lq >> 1);
    const bool oddlq = (lq & 1);

    // ---------------- chunk-PAIR loop: A-frags loaded once per pair ----------------
    #pragma unroll 1
    for (int p = 0; p < 4; p++) {
        CP_WAIT0();
        __syncthreads();   // [T0] WB0=Wv(2p), WB1=Wv(2p+1) visible; prev pair fully done

        // Vproj both chunks of the pair; A LDSM'd once
        float Cv0[4][4], Cv1[4][4];
        #pragma unroll
        for (int n = 0; n < 4; n++) {
            Cv0[n][0] = Cv0[n][1] = Cv0[n][2] = Cv0[n][3] = 0.f;
            Cv1[n][0] = Cv1[n][1] = Cv1[n][2] = Cv1[n][3] = 0.f;
        }
        #pragma unroll 4
        for (int kt = 0; kt < 16; kt++) {
            uint4 A = ldsm_x4(sb + XP_OFF + aSel + kt * 32);
            #pragma unroll
            for (int ntp = 0; ntp < 2; ntp++) {
                uint4 B0 = ldsm_x4(sb + WB0 + bSelX + (unsigned)(ntp * 16) * XSTR + kt * 32);
                uint4 B1 = ldsm_x4(sb + WB1 + bSelX + (unsigned)(ntp * 16) * XSTR + kt * 32);
                mma16816(Cv0[2 * ntp],     A.x, A.y, A.z, A.w, B0.x, B0.y);
                mma16816(Cv0[2 * ntp + 1], A.x, A.y, A.z, A.w, B0.z, B0.w);
                mma16816(Cv1[2 * ntp],     A.x, A.y, A.z, A.w, B1.x, B1.y);
                mma16816(Cv1[2 * ntp + 1], A.x, A.y, A.z, A.w, B1.z, B1.w);
            }
        }
        // VT(2p) store (prev pair's AV reads finished before T0)
        #pragma unroll
        for (int nt = 0; nt < 4; nt++) {
            float v0 = Cv0[nt][0], v1 = Cv0[nt][1], v2 = Cv0[nt][2], v3 = Cv0[nt][3];
            float sendA = oddlq ? v0 : v1;
            float recvA = __shfl_xor_sync(0xffffffffu, sendA, 4);
            float sendB = oddlq ? v2 : v3;
            float recvB = __shfl_xor_sync(0xffffffffu, sendB, 4);
            float a0 = oddlq ? recvA : v0, a1 = oddlq ? v1 : recvA;
            float b0 = oddlq ? recvB : v2, b1 = oddlq ? v3 : recvB;
            unsigned cc = (unsigned)(nt * 8 + 2 * q + (oddlq ? 1 : 0)) * VSTR;
            *(uint32_t*)(sm + VT_OFF + cc + (unsigned)(R + j2) * 2)     = packh(a0, a1);
            *(uint32_t*)(sm + VT_OFF + cc + (unsigned)(R + 8 + j2) * 2) = packh(b0, b1);
        }
        __syncthreads();   // [T1] Vproj reads of WB done; VT(2p) visible

        if (p < 3) {   // prefetch next pair into the now-free weight buffers
            const unsigned char* s0p = g_wimg + (unsigned)(2 * p + 4) * WCHUNK;
            const unsigned char* s1p = g_wimg + (unsigned)(2 * p + 5) * WCHUNK;
            for (int i = t; i < WCHUNK / 16; i += NTHR) {
                cp16(sm + WB0 + i * 16, s0p + i * 16);
                cp16(sm + WB1 + i * 16, s1p + i * 16);
            }
            CP_COMMIT();
        }

        // ---- AV(2p) + epilogue ----
        {
            float Co[4][4];
            #pragma unroll
            for (int n = 0; n < 4; n++) { Co[n][0] = Co[n][1] = Co[n][2] = Co[n][3] = 0.f; }
            #pragma unroll
            for (int kt = 0; kt < 8; kt++) {
                #pragma unroll
                for (int ntp = 0; ntp < 2; ntp++) {
                    uint4 B = ldsm_x4(sb + VT_OFF + bSelV + (unsigned)(ntp * 16) * VSTR + kt * 32);
                    mma16816(Co[2 * ntp],     ah[kt][0], ah[kt][1], ah[kt][2], ah[kt][3], B.x, B.y);
                    mma16816(Co[2 * ntp + 1], ah[kt][0], ah[kt][1], ah[kt][2], ah[kt][3], B.z, B.w);
                }
            }
            #pragma unroll
            for (int nt = 0; nt < 4; nt++) {
                int col = (2 * p) * 32 + nt * 8 + 2 * q;
                float2 bb = *(const float2*)(bv + col);
                *(float2*)(Og + (long long)(R + lq) * 256 + col) =
                    make_float2(Co[nt][0] + bb.x, Co[nt][1] + bb.y);
                *(float2*)(Og + (long long)(R + 8 + lq) * 256 + col) =
                    make_float2(Co[nt][2] + bb.x, Co[nt][3] + bb.y);
            }
        }
        __syncthreads();   // [T2] AV(2p) VT reads done

        // VT(2p+1) store
        #pragma unroll
        for (int nt = 0; nt < 4; nt++) {
            float v0 = Cv1[nt][0], v1 = Cv1[nt][1], v2 = Cv1[nt][2], v3 = Cv1[nt][3];
            float sendA = oddlq ? v0 : v1;
            float recvA = __shfl_xor_sync(0xffffffffu, sendA, 4);
            float sendB = oddlq ? v2 : v3;
            float recvB = __shfl_xor_sync(0xffffffffu, sendB, 4);
            float a0 = oddlq ? recvA : v0, a1 = oddlq ? v1 : recvA;
            float b0 = oddlq ? recvB : v2, b1 = oddlq ? v3 : recvB;
            unsigned cc = (unsigned)(nt * 8 + 2 * q + (oddlq ? 1 : 0)) * VSTR;
            *(uint32_t*)(sm + VT_OFF + cc + (unsigned)(R + j2) * 2)     = packh(a0, a1);
            *(uint32_t*)(sm + VT_OFF + cc + (unsigned)(R + 8 + j2) * 2) = packh(b0, b1);
        }
        __syncthreads();   // [T3] VT(2p+1) visible

        // ---- AV(2p+1) + epilogue ----
        {
            float Co[4][4];
            #pragma unroll
            for (int n = 0; n < 4; n++) { Co[n][0] = Co[n][1] = Co[n][2] = Co[n][3] = 0.f; }
            #pragma unroll
            for (int kt = 0; kt < 8; kt++) {
                #pragma unroll
                for (int ntp = 0; ntp < 2; ntp++) {
                    uint4 B = ldsm_x4(sb + VT_OFF + bSelV + (unsigned)(ntp * 16) * VSTR + kt * 32);
                    mma16816(Co[2 * ntp],     ah[kt][0], ah[kt][1], ah[kt][2], ah[kt][3], B.x, B.y);
                    mma16816(Co[2 * ntp + 1], ah[kt][0], ah[kt][1], ah[kt][2], ah[kt][3], B.z, B.w);
                }
            }
            #pragma unroll
            for (int nt = 0; nt < 4; nt++) {
                int col = (2 * p + 1) * 32 + nt * 8 + 2 * q;
                float2 bb = *(const float2*)(bv + col);
                *(float2*)(Og + (long long)(R + lq) * 256 + col) =
                    make_float2(Co[nt][0] + bb.x, Co[nt][1] + bb.y);
                *(float2*)(Og + (long long)(R + 8 + lq) * 256 + col) =
                    make_float2(Co[nt][2] + bb.x, Co[nt][3] + bb.y);
            }
        }
    }
}

extern "C" void kernel_launch(void* const* d_in, const int* in_sizes, int n_in,
                              void* d_out, int out_size) {
    const float* X  = (const float*)d_in[0];
    const float* Wq = (const float*)d_in[1];
    const float* bq = (const float*)d_in[2];
    const float* Wk = (const float*)d_in[3];
    const float* bk = (const float*)d_in[4];
    const float* Wv = (const float*)d_in[5];
    const float* bv = (const float*)d_in[6];
    float* out = (float*)d_out;

    const int groups = in_sizes[0] / (128 * 256);   // 2048

    prep_weights<<<320, 256>>>(Wq, Wk, Wv);

    cudaFuncSetAttribute(attn_mma_kernel,
                         cudaFuncAttributeMaxDynamicSharedMemorySize, SMEM_BYTES);
    attn_mma_kernel<<<groups, NTHR, SMEM_BYTES>>>(X, bq, bk, bv, out);
}